// round 13
// baseline (speedup 1.0000x reference)
#include <cuda_runtime.h>
#include <cuda_bf16.h>
#include <cstdint>

// B=2048, Q=128, S=128(K), H=32(N)
#define NB 2048
#define NQ 128
#define NS 128
#define NH 32
#define NC (NQ * NS)
#define TPB 128

__device__ __forceinline__ uint32_t smem_u32(const void* p) {
    uint32_t a;
    asm("{ .reg .u64 t; cvta.to.shared.u64 t, %1; cvt.u32.u64 %0, t; }" : "=r"(a) : "l"(p));
    return a;
}
__device__ __forceinline__ void ldsm4(uint32_t* r, uint32_t addr) {
    asm volatile("ldmatrix.sync.aligned.m8n8.x4.shared.b16 {%0,%1,%2,%3}, [%4];"
                 : "=r"(r[0]), "=r"(r[1]), "=r"(r[2]), "=r"(r[3]) : "r"(addr));
}
__device__ __forceinline__ void mma_bf16(float* d, const uint32_t* a, uint32_t b0, uint32_t b1) {
    asm volatile(
        "mma.sync.aligned.m16n8k16.row.col.f32.bf16.bf16.f32 "
        "{%0,%1,%2,%3}, {%4,%5,%6,%7}, {%8,%9}, {%0,%1,%2,%3};"
        : "+f"(d[0]), "+f"(d[1]), "+f"(d[2]), "+f"(d[3])
        : "r"(a[0]), "r"(a[1]), "r"(a[2]), "r"(a[3]), "r"(b0), "r"(b1));
}
// pack {hi half = y, lo half = x} as bf16x2
__device__ __forceinline__ uint32_t bf2pack(float x, float y) {
    uint32_t r;
    asm("cvt.rn.bf16x2.f32 %0, %1, %2;" : "=r"(r) : "f"(y), "f"(x));
    return r;
}

// Base = R9 (best: 36.9us). A smem: per-warp 32 rows x 64B, swizzle g^((r>>1)&3);
// B smem: 32 rows x 256B full-K, swizzle g^(r&7); both STS/LDSM conflict-free.
// R13 change: phased fragment loading inside each k16 step (peak frag liveness
// 48 -> 24 regs) + launch_bounds(128,5) for 5 CTAs/SM (occupancy, not structure:
// double-buffering was falsified in R11/R12).

__global__ __launch_bounds__(TPB, 5) void divenc_mma(
    const float* __restrict__ x, const float* __restrict__ W1,
    const float* __restrict__ b1, const float* __restrict__ W2,
    const float* __restrict__ b2, float* __restrict__ out)
{
    __shared__ __align__(16) __nv_bfloat16 sAhi[4][32 * 32];  // 8KB
    __shared__ __align__(16) __nv_bfloat16 sAlo[4][32 * 32];  // 8KB
    __shared__ __align__(16) __nv_bfloat16 sBhi[NH * NS];     // 8KB
    __shared__ __align__(16) __nv_bfloat16 sBlo[NH * NS];     // 8KB
    __shared__ float sB1[NH], sW2[NH];
    __shared__ float sB2v;

    const int q = blockIdx.x;
    const int bt = blockIdx.y;
    const int t = threadIdx.x;
    const int w = t >> 5;
    const int l = t & 31;

    // LDG/STS mapping for x: instr i covers warp-local rows 4i..4i+3;
    // lane l -> row 4i + (l>>3), float cols (l&7)*4 .. +3
    const int rl = l >> 3;
    const int cl = (l & 7) * 4;
    const float* xr = x + (size_t)bt * 128 * NC + (size_t)(32 * w + rl) * NC
                        + (size_t)q * NS + cl;

    // ---- prefetch x chunk 0 FIRST: DRAM latency hides under B staging ----
    float4 g[8];
    #pragma unroll
    for (int i = 0; i < 8; i++)
        g[i] = *(const float4*)(xr + (size_t)(4 * i) * NC);

    // ---- stage B = W1[q]^T full-K (hi/lo bf16, swizzled), conflict-free ----
    const float* gW = W1 + (size_t)q * NS * NH;
    char* bHiC = (char*)sBhi;
    char* bLoC = (char*)sBlo;
    #pragma unroll
    for (int i = 0; i < 4; i++) {
        int ko = 4 * i + w;                       // k-octet 0..15
        const float* wp = gW + (size_t)(ko * 8) * NH + l;  // h = l
        float wv[8];
        #pragma unroll
        for (int j = 0; j < 8; j++) wv[j] = wp[j * NH];
        uint32_t hh[4], ll[4];
        #pragma unroll
        for (int j = 0; j < 4; j++) {
            uint32_t hp = bf2pack(wv[2 * j], wv[2 * j + 1]);
            float e0 = wv[2 * j]     - __uint_as_float(hp << 16);
            float e1 = wv[2 * j + 1] - __uint_as_float(hp & 0xFFFF0000u);
            hh[j] = hp;
            ll[j] = bf2pack(e0, e1);
        }
        uint32_t sw = (uint32_t)(l * 256) + (uint32_t)(((ko ^ (l & 7)) << 4));
        *(uint4*)(bHiC + sw) = make_uint4(hh[0], hh[1], hh[2], hh[3]);
        *(uint4*)(bLoC + sw) = make_uint4(ll[0], ll[1], ll[2], ll[3]);
    }
    if (t < NH) { sB1[t] = b1[q * NH + t]; sW2[t] = W2[q * NH + t]; }
    if (t == 0) sB2v = b2[q];
    __syncthreads();   // the ONLY block-wide barrier

    float acc[2][4][4];
    #pragma unroll
    for (int mi = 0; mi < 2; mi++)
        #pragma unroll
        for (int nj = 0; nj < 4; nj++)
            #pragma unroll
            for (int c = 0; c < 4; c++) acc[mi][nj][c] = 0.0f;

    // ldmatrix lane params (non-trans, verified mapping)
    const int lr = l & 15;
    const int lkg = l >> 4;       // k-granule half: 0 -> k0-7, 1 -> k8-15
    const uint32_t vA = (uint32_t)((lr >> 1) & 3);
    const uint32_t vB = (uint32_t)(lr & 7);
    const uint32_t aHi = smem_u32(&sAhi[w][0]) + (uint32_t)lr * 64;
    const uint32_t aLo = smem_u32(&sAlo[w][0]) + (uint32_t)lr * 64;
    const uint32_t bHi = smem_u32(sBhi) + (uint32_t)lr * 256;
    const uint32_t bLo = smem_u32(sBlo) + (uint32_t)lr * 256;

    const int kbsts = cl * 2;                       // byte col of this lane's 8B
    const uint32_t gsts = (uint32_t)(kbsts >> 4);   // granule
    const uint32_t hsts = (uint32_t)(kbsts & 15);
    char* aHiW = (char*)&sAhi[w][0];
    char* aLoW = (char*)&sAlo[w][0];

    for (int c = 0; c < 4; c++) {
        // ---- convert + swizzled STS into warp-private region ----
        #pragma unroll
        for (int i = 0; i < 8; i++) {
            float4 v = g[i];
            uint32_t h01 = bf2pack(v.x, v.y);
            uint32_t h23 = bf2pack(v.z, v.w);
            float e0 = v.x - __uint_as_float(h01 << 16);
            float e1 = v.y - __uint_as_float(h01 & 0xFFFF0000u);
            float e2 = v.z - __uint_as_float(h23 << 16);
            float e3 = v.w - __uint_as_float(h23 & 0xFFFF0000u);
            uint32_t l01 = bf2pack(e0, e1);
            uint32_t l23 = bf2pack(e2, e3);
            int r = 4 * i + rl;
            uint32_t sw = (uint32_t)(r << 6)
                        + (((gsts ^ (uint32_t)((r >> 1) & 3)) << 4)) + hsts;
            *(uint2*)(aHiW + sw) = make_uint2(h01, h23);
            *(uint2*)(aLoW + sw) = make_uint2(l01, l23);
        }
        // ---- prefetch next chunk under this chunk's MMAs ----
        if (c < 3) {
            #pragma unroll
            for (int i = 0; i < 8; i++)
                g[i] = *(const float4*)(xr + (size_t)(4 * i) * NC + (c + 1) * 32);
        }
        __syncwarp();

        // ---- 2 k16 steps of MMA, phased to cap fragment liveness at 24 ----
        #pragma unroll
        for (int ks = 0; ks < 2; ks++) {
            const uint32_t gA = (uint32_t)(2 * ks + lkg);          // A k-granule (chunk-local)
            const uint32_t gB = (uint32_t)(4 * c + 2 * ks + lkg);  // B k-granule (global K)
            const uint32_t aoff = ((gA ^ vA) << 4);
            const uint32_t boff = ((gB ^ vB) << 4);

            // phase 1: A-hi, B-hi -> hi*hi
            uint32_t ah0[4], ah1[4], bh0[4], bh1[4];
            ldsm4(ah0, aHi + aoff);
            ldsm4(ah1, aHi + aoff + 16 * 64);
            ldsm4(bh0, bHi + boff);
            ldsm4(bh1, bHi + boff + 16 * 256);
            mma_bf16(acc[0][0], ah0, bh0[0], bh0[2]);
            mma_bf16(acc[1][0], ah1, bh0[0], bh0[2]);
            mma_bf16(acc[0][1], ah0, bh0[1], bh0[3]);
            mma_bf16(acc[1][1], ah1, bh0[1], bh0[3]);
            mma_bf16(acc[0][2], ah0, bh1[0], bh1[2]);
            mma_bf16(acc[1][2], ah1, bh1[0], bh1[2]);
            mma_bf16(acc[0][3], ah0, bh1[1], bh1[3]);
            mma_bf16(acc[1][3], ah1, bh1[1], bh1[3]);

            // phase 2: B-lo -> hi*lo (A-hi dies after this)
            uint32_t bl0[4], bl1[4];
            ldsm4(bl0, bLo + boff);
            ldsm4(bl1, bLo + boff + 16 * 256);
            mma_bf16(acc[0][0], ah0, bl0[0], bl0[2]);
            mma_bf16(acc[1][0], ah1, bl0[0], bl0[2]);
            mma_bf16(acc[0][1], ah0, bl0[1], bl0[3]);
            mma_bf16(acc[1][1], ah1, bl0[1], bl0[3]);
            mma_bf16(acc[0][2], ah0, bl1[0], bl1[2]);
            mma_bf16(acc[1][2], ah1, bl1[0], bl1[2]);
            mma_bf16(acc[0][3], ah0, bl1[1], bl1[3]);
            mma_bf16(acc[1][3], ah1, bl1[1], bl1[3]);

            // phase 3: A-lo -> lo*hi (B-hi still live; B-lo dead)
            uint32_t al0[4], al1[4];
            ldsm4(al0, aLo + aoff);
            ldsm4(al1, aLo + aoff + 16 * 64);
            mma_bf16(acc[0][0], al0, bh0[0], bh0[2]);
            mma_bf16(acc[1][0], al1, bh0[0], bh0[2]);
            mma_bf16(acc[0][1], al0, bh0[1], bh0[3]);
            mma_bf16(acc[1][1], al1, bh0[1], bh0[3]);
            mma_bf16(acc[0][2], al0, bh1[0], bh1[2]);
            mma_bf16(acc[1][2], al1, bh1[0], bh1[2]);
            mma_bf16(acc[0][3], al0, bh1[1], bh1[3]);
            mma_bf16(acc[1][3], al1, bh1[1], bh1[3]);
        }
        __syncwarp();  // LDSM of chunk c done before STS of chunk c+1
    }

    // ---- epilogue: +b1, ELU, dot W2, quad-reduce, store ----
    const int gg = l >> 2;
    const int qd = l & 3;
    #pragma unroll
    for (int mi = 0; mi < 2; mi++) {
        float pa = 0.0f, pb = 0.0f;
        #pragma unroll
        for (int nj = 0; nj < 4; nj++) {
            int h0 = nj * 8 + qd * 2, h1 = h0 + 1;
            float b10 = sB1[h0], b11 = sB1[h1];
            float w20 = sW2[h0], w21 = sW2[h1];
            float v0 = acc[mi][nj][0] + b10;
            float v1 = acc[mi][nj][1] + b11;
            float v2 = acc[mi][nj][2] + b10;
            float v3 = acc[mi][nj][3] + b11;
            pa += ((v0 > 0.0f) ? v0 : (__expf(v0) - 1.0f)) * w20;
            pa += ((v1 > 0.0f) ? v1 : (__expf(v1) - 1.0f)) * w21;
            pb += ((v2 > 0.0f) ? v2 : (__expf(v2) - 1.0f)) * w20;
            pb += ((v3 > 0.0f) ? v3 : (__expf(v3) - 1.0f)) * w21;
        }
        pa += __shfl_xor_sync(0xFFFFFFFFu, pa, 1);
        pa += __shfl_xor_sync(0xFFFFFFFFu, pa, 2);
        pb += __shfl_xor_sync(0xFFFFFFFFu, pb, 1);
        pb += __shfl_xor_sync(0xFFFFFFFFu, pb, 2);
        if (qd == 0) {
            int r0 = w * 32 + mi * 16 + gg;
            out[((size_t)bt * 128 + r0) * NQ + q] = pa + sB2v;
            out[((size_t)bt * 128 + r0 + 8) * NQ + q] = pb + sB2v;
        }
    }
}

extern "C" void kernel_launch(void* const* d_in, const int* in_sizes, int n_in,
                              void* d_out, int out_size) {
    const float* x  = (const float*)d_in[0];
    const float* W1 = (const float*)d_in[1];
    const float* b1 = (const float*)d_in[2];
    const float* W2 = (const float*)d_in[3];
    const float* b2 = (const float*)d_in[4];
    float* out = (float*)d_out;

    dim3 grid(NQ, NB / 128);  // 128 q x 16 batch tiles
    divenc_mma<<<grid, TPB>>>(x, W1, b1, W2, b2, out);
}

// round 14
// speedup vs baseline: 1.0539x; 1.0539x over previous
#include <cuda_runtime.h>
#include <cuda_bf16.h>
#include <cstdint>

// B=2048, Q=128, S=128(K), H=32(N)
#define NB 2048
#define NQ 128
#define NS 128
#define NH 32
#define NC (NQ * NS)
#define TPB 128

__device__ __forceinline__ uint32_t smem_u32(const void* p) {
    uint32_t a;
    asm("{ .reg .u64 t; cvta.to.shared.u64 t, %1; cvt.u32.u64 %0, t; }" : "=r"(a) : "l"(p));
    return a;
}
__device__ __forceinline__ void ldsm4(uint32_t* r, uint32_t addr) {
    asm volatile("ldmatrix.sync.aligned.m8n8.x4.shared.b16 {%0,%1,%2,%3}, [%4];"
                 : "=r"(r[0]), "=r"(r[1]), "=r"(r[2]), "=r"(r[3]) : "r"(addr));
}
__device__ __forceinline__ void mma_bf16(float* d, const uint32_t* a, uint32_t b0, uint32_t b1) {
    asm volatile(
        "mma.sync.aligned.m16n8k16.row.col.f32.bf16.bf16.f32 "
        "{%0,%1,%2,%3}, {%4,%5,%6,%7}, {%8,%9}, {%0,%1,%2,%3};"
        : "+f"(d[0]), "+f"(d[1]), "+f"(d[2]), "+f"(d[3])
        : "r"(a[0]), "r"(a[1]), "r"(a[2]), "r"(a[3]), "r"(b0), "r"(b1));
}
// pack {hi half = y, lo half = x} as bf16x2
__device__ __forceinline__ uint32_t bf2pack(float x, float y) {
    uint32_t r;
    asm("cvt.rn.bf16x2.f32 %0, %1, %2;" : "=r"(r) : "f"(y), "f"(x));
    return r;
}

// Base = R9 (best: 36.9us; kernel is an x-stream: dur = 134MB / achieved BW).
// R14: raise sustained MLP/occupancy without R13's serial-LDSM mistake:
//  (1) LDG for chunk c+1 interleaved INTO the convert loop (early, spread issue)
//  (2) 2-phase fragments: batch {Ahi,Alo,Bhi} LDSMs -> 16 MMAs -> {Blo} -> 8 MMAs
//      (peak frag liveness 24; only ONE extra serial LDSM point vs R9)
//  (3) launch_bounds(128,5): 5 CTAs/SM, 20 warps.
// A smem: per-warp 32 rows x 64B, swizzle g^((r>>1)&3);
// B smem: 32 rows x 256B full-K, swizzle g^(r&7); both STS/LDSM conflict-free.

__global__ __launch_bounds__(TPB, 5) void divenc_mma(
    const float* __restrict__ x, const float* __restrict__ W1,
    const float* __restrict__ b1, const float* __restrict__ W2,
    const float* __restrict__ b2, float* __restrict__ out)
{
    __shared__ __align__(16) __nv_bfloat16 sAhi[4][32 * 32];  // 8KB
    __shared__ __align__(16) __nv_bfloat16 sAlo[4][32 * 32];  // 8KB
    __shared__ __align__(16) __nv_bfloat16 sBhi[NH * NS];     // 8KB
    __shared__ __align__(16) __nv_bfloat16 sBlo[NH * NS];     // 8KB
    __shared__ float sB1[NH], sW2[NH];
    __shared__ float sB2v;

    const int q = blockIdx.x;
    const int bt = blockIdx.y;
    const int t = threadIdx.x;
    const int w = t >> 5;
    const int l = t & 31;

    // LDG/STS mapping for x: instr i covers warp-local rows 4i..4i+3;
    // lane l -> row 4i + (l>>3), float cols (l&7)*4 .. +3
    const int rl = l >> 3;
    const int cl = (l & 7) * 4;
    const float* xr = x + (size_t)bt * 128 * NC + (size_t)(32 * w + rl) * NC
                        + (size_t)q * NS + cl;

    // ---- prefetch x chunk 0 FIRST: DRAM latency hides under B staging ----
    float4 g[8];
    #pragma unroll
    for (int i = 0; i < 8; i++)
        g[i] = *(const float4*)(xr + (size_t)(4 * i) * NC);

    // ---- stage B = W1[q]^T full-K (hi/lo bf16, swizzled), conflict-free ----
    const float* gW = W1 + (size_t)q * NS * NH;
    char* bHiC = (char*)sBhi;
    char* bLoC = (char*)sBlo;
    #pragma unroll
    for (int i = 0; i < 4; i++) {
        int ko = 4 * i + w;                       // k-octet 0..15
        const float* wp = gW + (size_t)(ko * 8) * NH + l;  // h = l
        float wv[8];
        #pragma unroll
        for (int j = 0; j < 8; j++) wv[j] = wp[j * NH];
        uint32_t hh[4], ll[4];
        #pragma unroll
        for (int j = 0; j < 4; j++) {
            uint32_t hp = bf2pack(wv[2 * j], wv[2 * j + 1]);
            float e0 = wv[2 * j]     - __uint_as_float(hp << 16);
            float e1 = wv[2 * j + 1] - __uint_as_float(hp & 0xFFFF0000u);
            hh[j] = hp;
            ll[j] = bf2pack(e0, e1);
        }
        uint32_t sw = (uint32_t)(l * 256) + (uint32_t)(((ko ^ (l & 7)) << 4));
        *(uint4*)(bHiC + sw) = make_uint4(hh[0], hh[1], hh[2], hh[3]);
        *(uint4*)(bLoC + sw) = make_uint4(ll[0], ll[1], ll[2], ll[3]);
    }
    if (t < NH) { sB1[t] = b1[q * NH + t]; sW2[t] = W2[q * NH + t]; }
    if (t == 0) sB2v = b2[q];
    __syncthreads();   // the ONLY block-wide barrier

    float acc[2][4][4];
    #pragma unroll
    for (int mi = 0; mi < 2; mi++)
        #pragma unroll
        for (int nj = 0; nj < 4; nj++)
            #pragma unroll
            for (int c = 0; c < 4; c++) acc[mi][nj][c] = 0.0f;

    // ldmatrix lane params (non-trans, verified mapping)
    const int lr = l & 15;
    const int lkg = l >> 4;       // k-granule half: 0 -> k0-7, 1 -> k8-15
    const uint32_t vA = (uint32_t)((lr >> 1) & 3);
    const uint32_t vB = (uint32_t)(lr & 7);
    const uint32_t aHi = smem_u32(&sAhi[w][0]) + (uint32_t)lr * 64;
    const uint32_t aLo = smem_u32(&sAlo[w][0]) + (uint32_t)lr * 64;
    const uint32_t bHi = smem_u32(sBhi) + (uint32_t)lr * 256;
    const uint32_t bLo = smem_u32(sBlo) + (uint32_t)lr * 256;

    const int kbsts = cl * 2;                       // byte col of this lane's 8B
    const uint32_t gsts = (uint32_t)(kbsts >> 4);   // granule
    const uint32_t hsts = (uint32_t)(kbsts & 15);
    char* aHiW = (char*)&sAhi[w][0];
    char* aLoW = (char*)&sAlo[w][0];

    for (int c = 0; c < 4; c++) {
        // ---- convert + STS, with chunk c+1's LDG interleaved (early issue) ----
        #pragma unroll
        for (int i = 0; i < 8; i++) {
            float4 v = g[i];
            if (c < 3)   // reload g[i] immediately -> LDG issues early, spread out
                g[i] = *(const float4*)(xr + (size_t)(4 * i) * NC + (c + 1) * 32);
            uint32_t h01 = bf2pack(v.x, v.y);
            uint32_t h23 = bf2pack(v.z, v.w);
            float e0 = v.x - __uint_as_float(h01 << 16);
            float e1 = v.y - __uint_as_float(h01 & 0xFFFF0000u);
            float e2 = v.z - __uint_as_float(h23 << 16);
            float e3 = v.w - __uint_as_float(h23 & 0xFFFF0000u);
            uint32_t l01 = bf2pack(e0, e1);
            uint32_t l23 = bf2pack(e2, e3);
            int r = 4 * i + rl;
            uint32_t sw = (uint32_t)(r << 6)
                        + (((gsts ^ (uint32_t)((r >> 1) & 3)) << 4)) + hsts;
            *(uint2*)(aHiW + sw) = make_uint2(h01, h23);
            *(uint2*)(aLoW + sw) = make_uint2(l01, l23);
        }
        __syncwarp();

        // ---- 2 k16 steps, 2-phase fragment loading ----
        #pragma unroll
        for (int ks = 0; ks < 2; ks++) {
            const uint32_t gA = (uint32_t)(2 * ks + lkg);          // A k-granule (chunk-local)
            const uint32_t gB = (uint32_t)(4 * c + 2 * ks + lkg);  // B k-granule (global K)
            const uint32_t aoff = ((gA ^ vA) << 4);
            const uint32_t boff = ((gB ^ vB) << 4);

            // phase 1: batch 6 LDSMs (latencies overlap), then 16 MMAs
            uint32_t ah0[4], ah1[4], al0[4], al1[4], bh0[4], bh1[4];
            ldsm4(ah0, aHi + aoff);
            ldsm4(ah1, aHi + aoff + 16 * 64);
            ldsm4(al0, aLo + aoff);
            ldsm4(al1, aLo + aoff + 16 * 64);
            ldsm4(bh0, bHi + boff);
            ldsm4(bh1, bHi + boff + 16 * 256);
            // hi*hi
            mma_bf16(acc[0][0], ah0, bh0[0], bh0[2]);
            mma_bf16(acc[1][0], ah1, bh0[0], bh0[2]);
            mma_bf16(acc[0][1], ah0, bh0[1], bh0[3]);
            mma_bf16(acc[1][1], ah1, bh0[1], bh0[3]);
            mma_bf16(acc[0][2], ah0, bh1[0], bh1[2]);
            mma_bf16(acc[1][2], ah1, bh1[0], bh1[2]);
            mma_bf16(acc[0][3], ah0, bh1[1], bh1[3]);
            mma_bf16(acc[1][3], ah1, bh1[1], bh1[3]);
            // lo*hi (al dies after this)
            mma_bf16(acc[0][0], al0, bh0[0], bh0[2]);
            mma_bf16(acc[1][0], al1, bh0[0], bh0[2]);
            mma_bf16(acc[0][1], al0, bh0[1], bh0[3]);
            mma_bf16(acc[1][1], al1, bh0[1], bh0[3]);
            mma_bf16(acc[0][2], al0, bh1[0], bh1[2]);
            mma_bf16(acc[1][2], al1, bh1[0], bh1[2]);
            mma_bf16(acc[0][3], al0, bh1[1], bh1[3]);
            mma_bf16(acc[1][3], al1, bh1[1], bh1[3]);

            // phase 2: B-lo -> hi*lo
            uint32_t bl0[4], bl1[4];
            ldsm4(bl0, bLo + boff);
            ldsm4(bl1, bLo + boff + 16 * 256);
            mma_bf16(acc[0][0], ah0, bl0[0], bl0[2]);
            mma_bf16(acc[1][0], ah1, bl0[0], bl0[2]);
            mma_bf16(acc[0][1], ah0, bl0[1], bl0[3]);
            mma_bf16(acc[1][1], ah1, bl0[1], bl0[3]);
            mma_bf16(acc[0][2], ah0, bl1[0], bl1[2]);
            mma_bf16(acc[1][2], ah1, bl1[0], bl1[2]);
            mma_bf16(acc[0][3], ah0, bl1[1], bl1[3]);
            mma_bf16(acc[1][3], ah1, bl1[1], bl1[3]);
        }
        __syncwarp();  // LDSM of chunk c done before STS of chunk c+1
    }

    // ---- epilogue: +b1, ELU, dot W2, quad-reduce, store ----
    const int gg = l >> 2;
    const int qd = l & 3;
    #pragma unroll
    for (int mi = 0; mi < 2; mi++) {
        float pa = 0.0f, pb = 0.0f;
        #pragma unroll
        for (int nj = 0; nj < 4; nj++) {
            int h0 = nj * 8 + qd * 2, h1 = h0 + 1;
            float b10 = sB1[h0], b11 = sB1[h1];
            float w20 = sW2[h0], w21 = sW2[h1];
            float v0 = acc[mi][nj][0] + b10;
            float v1 = acc[mi][nj][1] + b11;
            float v2 = acc[mi][nj][2] + b10;
            float v3 = acc[mi][nj][3] + b11;
            pa += ((v0 > 0.0f) ? v0 : (__expf(v0) - 1.0f)) * w20;
            pa += ((v1 > 0.0f) ? v1 : (__expf(v1) - 1.0f)) * w21;
            pb += ((v2 > 0.0f) ? v2 : (__expf(v2) - 1.0f)) * w20;
            pb += ((v3 > 0.0f) ? v3 : (__expf(v3) - 1.0f)) * w21;
        }
        pa += __shfl_xor_sync(0xFFFFFFFFu, pa, 1);
        pa += __shfl_xor_sync(0xFFFFFFFFu, pa, 2);
        pb += __shfl_xor_sync(0xFFFFFFFFu, pb, 1);
        pb += __shfl_xor_sync(0xFFFFFFFFu, pb, 2);
        if (qd == 0) {
            int r0 = w * 32 + mi * 16 + gg;
            out[((size_t)bt * 128 + r0) * NQ + q] = pa + sB2v;
            out[((size_t)bt * 128 + r0 + 8) * NQ + q] = pb + sB2v;
        }
    }
}

extern "C" void kernel_launch(void* const* d_in, const int* in_sizes, int n_in,
                              void* d_out, int out_size) {
    const float* x  = (const float*)d_in[0];
    const float* W1 = (const float*)d_in[1];
    const float* b1 = (const float*)d_in[2];
    const float* W2 = (const float*)d_in[3];
    const float* b2 = (const float*)d_in[4];
    float* out = (float*)d_out;

    dim3 grid(NQ, NB / 128);  // 128 q x 16 batch tiles
    divenc_mma<<<grid, TPB>>>(x, W1, b1, W2, b2, out);
}

// round 15
// speedup vs baseline: 1.1865x; 1.1258x over previous
#include <cuda_runtime.h>
#include <cuda_bf16.h>
#include <cstdint>

// B=2048, Q=128, S=128(K), H=32(N)
#define NB 2048
#define NQ 128
#define NS 128
#define NH 32
#define NC (NQ * NS)
#define TPB 128

__device__ __forceinline__ uint32_t smem_u32(const void* p) {
    uint32_t a;
    asm("{ .reg .u64 t; cvta.to.shared.u64 t, %1; cvt.u32.u64 %0, t; }" : "=r"(a) : "l"(p));
    return a;
}
__device__ __forceinline__ void ldsm4(uint32_t* r, uint32_t addr) {
    asm volatile("ldmatrix.sync.aligned.m8n8.x4.shared.b16 {%0,%1,%2,%3}, [%4];"
                 : "=r"(r[0]), "=r"(r[1]), "=r"(r[2]), "=r"(r[3]) : "r"(addr));
}
__device__ __forceinline__ void mma_bf16(float* d, const uint32_t* a, uint32_t b0, uint32_t b1) {
    asm volatile(
        "mma.sync.aligned.m16n8k16.row.col.f32.bf16.bf16.f32 "
        "{%0,%1,%2,%3}, {%4,%5,%6,%7}, {%8,%9}, {%0,%1,%2,%3};"
        : "+f"(d[0]), "+f"(d[1]), "+f"(d[2]), "+f"(d[3])
        : "r"(a[0]), "r"(a[1]), "r"(a[2]), "r"(a[3]), "r"(b0), "r"(b1));
}
// pack {hi half = y, lo half = x} as bf16x2
__device__ __forceinline__ uint32_t bf2pack(float x, float y) {
    uint32_t r;
    asm("cvt.rn.bf16x2.f32 %0, %1, %2;" : "=r"(r) : "f"(y), "f"(x));
    return r;
}

// R15 = exact R9 (best: 36.9us) + two attribution-clean deltas:
//  (1) chunk c+1's LDG interleaved into the convert loop (early/spread issue,
//      continuous MLP — the x-stream is the whole kernel)
//  (2) repack arrays removed: B fragment regs fed directly to MMAs
// Phased LDSM (R13/R14) and double-buffering (R11/R12) are falsified; batch-8
// LDSM + launch_bounds(128,4) + grouped-by-nj MMA order kept bit-for-bit.
// A smem: per-warp 32 rows x 64B, swizzle g^((r>>1)&3);
// B smem: 32 rows x 256B full-K, swizzle g^(r&7); both STS/LDSM conflict-free.

__global__ __launch_bounds__(TPB, 4) void divenc_mma(
    const float* __restrict__ x, const float* __restrict__ W1,
    const float* __restrict__ b1, const float* __restrict__ W2,
    const float* __restrict__ b2, float* __restrict__ out)
{
    __shared__ __align__(16) __nv_bfloat16 sAhi[4][32 * 32];  // 8KB
    __shared__ __align__(16) __nv_bfloat16 sAlo[4][32 * 32];  // 8KB
    __shared__ __align__(16) __nv_bfloat16 sBhi[NH * NS];     // 8KB
    __shared__ __align__(16) __nv_bfloat16 sBlo[NH * NS];     // 8KB
    __shared__ float sB1[NH], sW2[NH];
    __shared__ float sB2v;

    const int q = blockIdx.x;
    const int bt = blockIdx.y;
    const int t = threadIdx.x;
    const int w = t >> 5;
    const int l = t & 31;

    // LDG/STS mapping for x: instr i covers warp-local rows 4i..4i+3;
    // lane l -> row 4i + (l>>3), float cols (l&7)*4 .. +3
    const int rl = l >> 3;
    const int cl = (l & 7) * 4;
    const float* xr = x + (size_t)bt * 128 * NC + (size_t)(32 * w + rl) * NC
                        + (size_t)q * NS + cl;

    // ---- prefetch x chunk 0 FIRST: DRAM latency hides under B staging ----
    float4 g[8];
    #pragma unroll
    for (int i = 0; i < 8; i++)
        g[i] = *(const float4*)(xr + (size_t)(4 * i) * NC);

    // ---- stage B = W1[q]^T full-K (hi/lo bf16, swizzled), conflict-free ----
    const float* gW = W1 + (size_t)q * NS * NH;
    char* bHiC = (char*)sBhi;
    char* bLoC = (char*)sBlo;
    #pragma unroll
    for (int i = 0; i < 4; i++) {
        int ko = 4 * i + w;                       // k-octet 0..15
        const float* wp = gW + (size_t)(ko * 8) * NH + l;  // h = l
        float wv[8];
        #pragma unroll
        for (int j = 0; j < 8; j++) wv[j] = wp[j * NH];
        uint32_t hh[4], ll[4];
        #pragma unroll
        for (int j = 0; j < 4; j++) {
            uint32_t hp = bf2pack(wv[2 * j], wv[2 * j + 1]);
            float e0 = wv[2 * j]     - __uint_as_float(hp << 16);
            float e1 = wv[2 * j + 1] - __uint_as_float(hp & 0xFFFF0000u);
            hh[j] = hp;
            ll[j] = bf2pack(e0, e1);
        }
        uint32_t sw = (uint32_t)(l * 256) + (uint32_t)(((ko ^ (l & 7)) << 4));
        *(uint4*)(bHiC + sw) = make_uint4(hh[0], hh[1], hh[2], hh[3]);
        *(uint4*)(bLoC + sw) = make_uint4(ll[0], ll[1], ll[2], ll[3]);
    }
    if (t < NH) { sB1[t] = b1[q * NH + t]; sW2[t] = W2[q * NH + t]; }
    if (t == 0) sB2v = b2[q];
    __syncthreads();   // the ONLY block-wide barrier

    float acc[2][4][4];
    #pragma unroll
    for (int mi = 0; mi < 2; mi++)
        #pragma unroll
        for (int nj = 0; nj < 4; nj++)
            #pragma unroll
            for (int c = 0; c < 4; c++) acc[mi][nj][c] = 0.0f;

    // ldmatrix lane params (non-trans, verified mapping)
    const int lr = l & 15;
    const int lkg = l >> 4;       // k-granule half: 0 -> k0-7, 1 -> k8-15
    const uint32_t vA = (uint32_t)((lr >> 1) & 3);
    const uint32_t vB = (uint32_t)(lr & 7);
    const uint32_t aHi = smem_u32(&sAhi[w][0]) + (uint32_t)lr * 64;
    const uint32_t aLo = smem_u32(&sAlo[w][0]) + (uint32_t)lr * 64;
    const uint32_t bHi = smem_u32(sBhi) + (uint32_t)lr * 256;
    const uint32_t bLo = smem_u32(sBlo) + (uint32_t)lr * 256;

    const int kbsts = cl * 2;                       // byte col of this lane's 8B
    const uint32_t gsts = (uint32_t)(kbsts >> 4);   // granule
    const uint32_t hsts = (uint32_t)(kbsts & 15);
    char* aHiW = (char*)&sAhi[w][0];
    char* aLoW = (char*)&sAlo[w][0];

    for (int c = 0; c < 4; c++) {
        // ---- convert + STS, with chunk c+1's LDG interleaved (early issue) ----
        #pragma unroll
        for (int i = 0; i < 8; i++) {
            float4 v = g[i];
            if (c < 3)   // reload g[i] immediately -> LDG issues early, spread out
                g[i] = *(const float4*)(xr + (size_t)(4 * i) * NC + (c + 1) * 32);
            uint32_t h01 = bf2pack(v.x, v.y);
            uint32_t h23 = bf2pack(v.z, v.w);
            float e0 = v.x - __uint_as_float(h01 << 16);
            float e1 = v.y - __uint_as_float(h01 & 0xFFFF0000u);
            float e2 = v.z - __uint_as_float(h23 << 16);
            float e3 = v.w - __uint_as_float(h23 & 0xFFFF0000u);
            uint32_t l01 = bf2pack(e0, e1);
            uint32_t l23 = bf2pack(e2, e3);
            int r = 4 * i + rl;
            uint32_t sw = (uint32_t)(r << 6)
                        + (((gsts ^ (uint32_t)((r >> 1) & 3)) << 4)) + hsts;
            *(uint2*)(aHiW + sw) = make_uint2(h01, h23);
            *(uint2*)(aLoW + sw) = make_uint2(l01, l23);
        }
        __syncwarp();

        // ---- 2 k16 steps of MMA: batch all 8 LDSMs, then 24 MMAs (R9 order) ----
        #pragma unroll
        for (int ks = 0; ks < 2; ks++) {
            const uint32_t gA = (uint32_t)(2 * ks + lkg);          // A k-granule (chunk-local)
            const uint32_t gB = (uint32_t)(4 * c + 2 * ks + lkg);  // B k-granule (global K)
            const uint32_t aoff = ((gA ^ vA) << 4);
            const uint32_t boff = ((gB ^ vB) << 4);
            uint32_t ah0[4], ah1[4], al0[4], al1[4];
            uint32_t bh0[4], bh1[4], bl0[4], bl1[4];
            ldsm4(ah0, aHi + aoff);
            ldsm4(ah1, aHi + aoff + 16 * 64);
            ldsm4(al0, aLo + aoff);
            ldsm4(al1, aLo + aoff + 16 * 64);
            ldsm4(bh0, bHi + boff);
            ldsm4(bh1, bHi + boff + 16 * 256);
            ldsm4(bl0, bLo + boff);
            ldsm4(bl1, bLo + boff + 16 * 256);
            // nj=0: b-pair (bh0[0],bh0[2]) / (bl0[0],bl0[2]); nj=1: [1],[3];
            // nj=2: bh1/bl1 [0],[2]; nj=3: [1],[3]  (same mapping as R9 repack)
            // per-nj order kept identical to R9: hi*hi, hi*lo, lo*hi
            mma_bf16(acc[0][0], ah0, bh0[0], bh0[2]);
            mma_bf16(acc[1][0], ah1, bh0[0], bh0[2]);
            mma_bf16(acc[0][0], ah0, bl0[0], bl0[2]);
            mma_bf16(acc[1][0], ah1, bl0[0], bl0[2]);
            mma_bf16(acc[0][0], al0, bh0[0], bh0[2]);
            mma_bf16(acc[1][0], al1, bh0[0], bh0[2]);

            mma_bf16(acc[0][1], ah0, bh0[1], bh0[3]);
            mma_bf16(acc[1][1], ah1, bh0[1], bh0[3]);
            mma_bf16(acc[0][1], ah0, bl0[1], bl0[3]);
            mma_bf16(acc[1][1], ah1, bl0[1], bl0[3]);
            mma_bf16(acc[0][1], al0, bh0[1], bh0[3]);
            mma_bf16(acc[1][1], al1, bh0[1], bh0[3]);

            mma_bf16(acc[0][2], ah0, bh1[0], bh1[2]);
            mma_bf16(acc[1][2], ah1, bh1[0], bh1[2]);
            mma_bf16(acc[0][2], ah0, bl1[0], bl1[2]);
            mma_bf16(acc[1][2], ah1, bl1[0], bl1[2]);
            mma_bf16(acc[0][2], al0, bh1[0], bh1[2]);
            mma_bf16(acc[1][2], al1, bh1[0], bh1[2]);

            mma_bf16(acc[0][3], ah0, bh1[1], bh1[3]);
            mma_bf16(acc[1][3], ah1, bh1[1], bh1[3]);
            mma_bf16(acc[0][3], ah0, bl1[1], bl1[3]);
            mma_bf16(acc[1][3], ah1, bl1[1], bl1[3]);
            mma_bf16(acc[0][3], al0, bh1[1], bh1[3]);
            mma_bf16(acc[1][3], al1, bh1[1], bh1[3]);
        }
        __syncwarp();  // LDSM of chunk c done before STS of chunk c+1
    }

    // ---- epilogue: +b1, ELU, dot W2, quad-reduce, store ----
    const int gg = l >> 2;
    const int qd = l & 3;
    #pragma unroll
    for (int mi = 0; mi < 2; mi++) {
        float pa = 0.0f, pb = 0.0f;
        #pragma unroll
        for (int nj = 0; nj < 4; nj++) {
            int h0 = nj * 8 + qd * 2, h1 = h0 + 1;
            float b10 = sB1[h0], b11 = sB1[h1];
            float w20 = sW2[h0], w21 = sW2[h1];
            float v0 = acc[mi][nj][0] + b10;
            float v1 = acc[mi][nj][1] + b11;
            float v2 = acc[mi][nj][2] + b10;
            float v3 = acc[mi][nj][3] + b11;
            pa += ((v0 > 0.0f) ? v0 : (__expf(v0) - 1.0f)) * w20;
            pa += ((v1 > 0.0f) ? v1 : (__expf(v1) - 1.0f)) * w21;
            pb += ((v2 > 0.0f) ? v2 : (__expf(v2) - 1.0f)) * w20;
            pb += ((v3 > 0.0f) ? v3 : (__expf(v3) - 1.0f)) * w21;
        }
        pa += __shfl_xor_sync(0xFFFFFFFFu, pa, 1);
        pa += __shfl_xor_sync(0xFFFFFFFFu, pa, 2);
        pb += __shfl_xor_sync(0xFFFFFFFFu, pb, 1);
        pb += __shfl_xor_sync(0xFFFFFFFFu, pb, 2);
        if (qd == 0) {
            int r0 = w * 32 + mi * 16 + gg;
            out[((size_t)bt * 128 + r0) * NQ + q] = pa + sB2v;
            out[((size_t)bt * 128 + r0 + 8) * NQ + q] = pb + sB2v;
        }
    }
}

extern "C" void kernel_launch(void* const* d_in, const int* in_sizes, int n_in,
                              void* d_out, int out_size) {
    const float* x  = (const float*)d_in[0];
    const float* W1 = (const float*)d_in[1];
    const float* b1 = (const float*)d_in[2];
    const float* W2 = (const float*)d_in[3];
    const float* b2 = (const float*)d_in[4];
    float* out = (float*)d_out;

    dim3 grid(NQ, NB / 128);  // 128 q x 16 batch tiles
    divenc_mma<<<grid, TPB>>>(x, W1, b1, W2, b2, out);
}